// round 1
// baseline (speedup 1.0000x reference)
#include <cuda_runtime.h>
#include <math.h>
#include <stdint.h>
#include <stddef.h>

// Problem constants
#define BATCH 16
#define NTOK  3136
#define CH    768
#define NH    16
#define HD    48

// Scratch (device globals; no runtime allocation allowed)
__device__ float g_qkv[(size_t)BATCH * NTOK * 3 * CH];   // [B*N, 2304]  (q|k|v per token)
__device__ float g_att[(size_t)BATCH * NTOK * CH];       // [B*N, 768]   attention output

// ---------------------------------------------------------------------------
// Classic 128x128x8 fp32 SGEMM, 256 threads, 8x8 per-thread micro-tile.
// All dims here are multiples of the tile sizes (M=50176, N in {2304,768}, K=768)
// so no bounds checks are needed.
// ---------------------------------------------------------------------------
__global__ __launch_bounds__(256) void sgemm128(
    const float* __restrict__ A, const float* __restrict__ B,
    float* __restrict__ C, int M, int N, int K,
    const float* __restrict__ bias)
{
    __shared__ float As[8][128];
    __shared__ float Bs[8][128];

    const int tid = threadIdx.x;
    const float* Ab = A + (size_t)blockIdx.y * 128 * (size_t)K;
    const float* Bb = B + (size_t)blockIdx.x * 128;
    float* Cb = C + (size_t)blockIdx.y * 128 * (size_t)N + (size_t)blockIdx.x * 128;

    const int aRow = tid >> 1;          // 0..127
    const int aCol = (tid & 1) << 2;    // 0 or 4
    const int bRow = tid >> 5;          // 0..7
    const int bCol = (tid & 31) << 2;   // 0..124
    const int tx = (tid & 15) << 3;     // col offset of micro-tile
    const int ty = (tid >> 4) << 3;     // row offset of micro-tile

    float acc[8][8];
#pragma unroll
    for (int i = 0; i < 8; i++)
#pragma unroll
        for (int j = 0; j < 8; j++) acc[i][j] = 0.f;

    for (int k0 = 0; k0 < K; k0 += 8) {
        float4 av = *(const float4*)(Ab + (size_t)aRow * K + (k0 + aCol));
        float4 bv = *(const float4*)(Bb + (size_t)(k0 + bRow) * N + bCol);
        As[aCol + 0][aRow] = av.x;
        As[aCol + 1][aRow] = av.y;
        As[aCol + 2][aRow] = av.z;
        As[aCol + 3][aRow] = av.w;
        *(float4*)&Bs[bRow][bCol] = bv;
        __syncthreads();
#pragma unroll
        for (int k = 0; k < 8; k++) {
            float4 a0 = *(const float4*)&As[k][ty];
            float4 a1 = *(const float4*)&As[k][ty + 4];
            float4 b0 = *(const float4*)&Bs[k][tx];
            float4 b1 = *(const float4*)&Bs[k][tx + 4];
            float ar[8] = {a0.x, a0.y, a0.z, a0.w, a1.x, a1.y, a1.z, a1.w};
            float br[8] = {b0.x, b0.y, b0.z, b0.w, b1.x, b1.y, b1.z, b1.w};
#pragma unroll
            for (int i = 0; i < 8; i++)
#pragma unroll
                for (int j = 0; j < 8; j++)
                    acc[i][j] = fmaf(ar[i], br[j], acc[i][j]);
        }
        __syncthreads();
    }

#pragma unroll
    for (int i = 0; i < 8; i++) {
        float* crow = Cb + (size_t)(ty + i) * N + tx;
        if (bias) {
            const float* brow = bias + (size_t)blockIdx.x * 128 + tx;
#pragma unroll
            for (int j = 0; j < 8; j++) acc[i][j] += brow[j];
        }
        float4 v0 = {acc[i][0], acc[i][1], acc[i][2], acc[i][3]};
        float4 v1 = {acc[i][4], acc[i][5], acc[i][6], acc[i][7]};
        *(float4*)(crow) = v0;
        *(float4*)(crow + 4) = v1;
    }
}

// ---------------------------------------------------------------------------
// Fused cross-covariance attention core: one CTA per (b,h).
// Phase 1: Gram matrix S[d][e] = sum_n q[n,d]*k[n,e] over N=3136, plus
//          per-d / per-e sums of squares accumulated for free.
// Phase 2: scale by 1/max(||q_d||,eps) * 1/max(||k_e||,eps) * temperature[h],
//          row softmax of 48x48.
// Phase 3: out[n, (h,d)] = sum_e attn[d][e] * v[n][e], streamed over tokens.
// ---------------------------------------------------------------------------
__global__ __launch_bounds__(256) void xca_kernel(const float* __restrict__ temperature)
{
    __shared__ float qs[32][48];
    __shared__ float ks[32][48];
    __shared__ float attn[48][52];
    __shared__ float invq[48];
    __shared__ float invk[48];

    const int bh = blockIdx.x;
    const int b = bh >> 4;
    const int h = bh & 15;
    const float* base = g_qkv + (size_t)b * NTOK * (3 * CH) + (size_t)h * HD;
    const int tid = threadIdx.x;
    const int r = tid >> 4;   // 0..15 -> d block (3 rows)
    const int c = tid & 15;   // 0..15 -> e block (3 cols)

    float acc[3][3];
#pragma unroll
    for (int i = 0; i < 3; i++)
#pragma unroll
        for (int j = 0; j < 3; j++) acc[i][j] = 0.f;
    float ssq[3] = {0.f, 0.f, 0.f};
    float ssk[3] = {0.f, 0.f, 0.f};

    for (int n0 = 0; n0 < NTOK; n0 += 32) {
        __syncthreads();
        // 32 tokens * 48 floats = 384 float4 each for q and k
#pragma unroll
        for (int i = 0; i < 2; i++) {
            int idx = tid + i * 256;
            if (idx < 384) {
                int n = idx / 12;
                int m = (idx % 12) * 4;
                const float* p = base + (size_t)(n0 + n) * (3 * CH) + m;
                *(float4*)&qs[n][m] = *(const float4*)p;          // q section
                *(float4*)&ks[n][m] = *(const float4*)(p + CH);   // k section
            }
        }
        __syncthreads();
#pragma unroll 2
        for (int n = 0; n < 32; n++) {
            float q0 = qs[n][3 * r], q1 = qs[n][3 * r + 1], q2 = qs[n][3 * r + 2];
            float k0 = ks[n][3 * c], k1 = ks[n][3 * c + 1], k2 = ks[n][3 * c + 2];
            acc[0][0] = fmaf(q0, k0, acc[0][0]);
            acc[0][1] = fmaf(q0, k1, acc[0][1]);
            acc[0][2] = fmaf(q0, k2, acc[0][2]);
            acc[1][0] = fmaf(q1, k0, acc[1][0]);
            acc[1][1] = fmaf(q1, k1, acc[1][1]);
            acc[1][2] = fmaf(q1, k2, acc[1][2]);
            acc[2][0] = fmaf(q2, k0, acc[2][0]);
            acc[2][1] = fmaf(q2, k1, acc[2][1]);
            acc[2][2] = fmaf(q2, k2, acc[2][2]);
            if (c == 0) {
                ssq[0] = fmaf(q0, q0, ssq[0]);
                ssq[1] = fmaf(q1, q1, ssq[1]);
                ssq[2] = fmaf(q2, q2, ssq[2]);
            }
            if (r == 0) {
                ssk[0] = fmaf(k0, k0, ssk[0]);
                ssk[1] = fmaf(k1, k1, ssk[1]);
                ssk[2] = fmaf(k2, k2, ssk[2]);
            }
        }
    }

    if (c == 0) {
        invq[3 * r + 0] = ssq[0];
        invq[3 * r + 1] = ssq[1];
        invq[3 * r + 2] = ssq[2];
    }
    if (r == 0) {
        invk[3 * c + 0] = ssk[0];
        invk[3 * c + 1] = ssk[1];
        invk[3 * c + 2] = ssk[2];
    }
    __syncthreads();
    if (tid < 48) {
        invq[tid] = 1.f / fmaxf(sqrtf(invq[tid]), 1e-12f);
    } else if (tid < 96) {
        invk[tid - 48] = 1.f / fmaxf(sqrtf(invk[tid - 48]), 1e-12f);
    }
    __syncthreads();

    const float temp = temperature[h];
#pragma unroll
    for (int i = 0; i < 3; i++)
#pragma unroll
        for (int j = 0; j < 3; j++)
            attn[3 * r + i][3 * c + j] =
                acc[i][j] * invq[3 * r + i] * invk[3 * c + j] * temp;
    __syncthreads();

    // Row softmax over 48 cols; warp w handles rows w, w+8, ...
    const int lane = tid & 31;
    const int w = tid >> 5;
    for (int d = w; d < 48; d += 8) {
        float x1 = attn[d][lane];
        float x2 = (lane < 16) ? attn[d][32 + lane] : -1e30f;
        float m = fmaxf(x1, x2);
#pragma unroll
        for (int o = 16; o > 0; o >>= 1)
            m = fmaxf(m, __shfl_xor_sync(0xffffffffu, m, o));
        float p1 = expf(x1 - m);
        float p2 = (lane < 16) ? expf(x2 - m) : 0.f;
        float s = p1 + p2;
#pragma unroll
        for (int o = 16; o > 0; o >>= 1)
            s += __shfl_xor_sync(0xffffffffu, s, o);
        float inv = 1.f / s;
        attn[d][lane] = p1 * inv;
        if (lane < 16) attn[d][32 + lane] = p2 * inv;
    }
    __syncthreads();

    // Phase 3: out[n, h*48+d] = sum_e attn[d][e] * v[n][e]
    float* outp = g_att + (size_t)b * NTOK * CH + (size_t)h * HD;
    const int d = tid % 48;
    const int vt = tid / 48;   // 0..3 active (tid < 192)
    float areg[48];
    if (tid < 192) {
#pragma unroll
        for (int e = 0; e < 48; e++) areg[e] = attn[d][e];
    }

    for (int n0 = 0; n0 < NTOK; n0 += 16) {
        __syncthreads();
        if (tid < 192) {
            int n = tid / 12;
            int m = (tid % 12) * 4;
            *(float4*)&qs[n][m] =
                *(const float4*)(base + (size_t)(n0 + n) * (3 * CH) + 2 * CH + m);
        }
        __syncthreads();
        if (tid < 192) {
            int nb = vt * 4;
            float o0 = 0.f, o1 = 0.f, o2 = 0.f, o3 = 0.f;
#pragma unroll
            for (int e = 0; e < 48; e++) {
                float a = areg[e];
                o0 = fmaf(a, qs[nb + 0][e], o0);
                o1 = fmaf(a, qs[nb + 1][e], o1);
                o2 = fmaf(a, qs[nb + 2][e], o2);
                o3 = fmaf(a, qs[nb + 3][e], o3);
            }
            outp[(size_t)(n0 + nb + 0) * CH + d] = o0;
            outp[(size_t)(n0 + nb + 1) * CH + d] = o1;
            outp[(size_t)(n0 + nb + 2) * CH + d] = o2;
            outp[(size_t)(n0 + nb + 3) * CH + d] = o3;
        }
    }
}

// ---------------------------------------------------------------------------
// Launch: GEMM1 (x @ qkv_w) -> fused XCA -> GEMM2 (att @ proj_w + b)
// ---------------------------------------------------------------------------
extern "C" void kernel_launch(void* const* d_in, const int* in_sizes, int n_in,
                              void* d_out, int out_size)
{
    const float* x           = (const float*)d_in[0];
    const float* qkv_w       = (const float*)d_in[1];
    const float* temperature = (const float*)d_in[2];
    const float* proj_w      = (const float*)d_in[3];
    const float* proj_b      = (const float*)d_in[4];
    float* out = (float*)d_out;

    float* qkv_d = nullptr;
    float* att_d = nullptr;
    cudaGetSymbolAddress((void**)&qkv_d, g_qkv);
    cudaGetSymbolAddress((void**)&att_d, g_att);

    const int M = BATCH * NTOK;  // 50176

    dim3 g1((3 * CH) / 128, M / 128);  // (18, 392)
    sgemm128<<<g1, 256>>>(x, qkv_w, qkv_d, M, 3 * CH, CH, nullptr);

    xca_kernel<<<BATCH * NH, 256>>>(temperature);

    dim3 g2(CH / 128, M / 128);        // (6, 392)
    sgemm128<<<g2, 256>>>(att_d, proj_w, out, M, CH, CH, proj_b);
}

// round 3
// speedup vs baseline: 2.2116x; 2.2116x over previous
#include <cuda_runtime.h>
#include <cuda_bf16.h>
#include <math.h>
#include <stdint.h>
#include <stddef.h>

typedef __nv_bfloat16 bf16;

#define BATCH 16
#define NTOK  3136
#define CH    768
#define NH    16
#define HD    48
#define KDIM  768
#define MROWS (BATCH*NTOK)   // 50176

// ----------------------------- device scratch ------------------------------
__device__ bf16  g_xhi[(size_t)MROWS * KDIM];
__device__ bf16  g_xlo[(size_t)MROWS * KDIM];
__device__ float g_qkv[(size_t)MROWS * 3 * CH];
__device__ bf16  g_ahi[(size_t)MROWS * CH];
__device__ bf16  g_alo[(size_t)MROWS * CH];
__device__ bf16  g_wqhi[(size_t)(3 * CH) * KDIM];
__device__ bf16  g_wqlo[(size_t)(3 * CH) * KDIM];
__device__ bf16  g_wphi[(size_t)CH * KDIM];
__device__ bf16  g_wplo[(size_t)CH * KDIM];

// ----------------------------- PTX helpers ---------------------------------
__device__ __forceinline__ uint32_t smem_u32(const void* p) {
    return (uint32_t)__cvta_generic_to_shared(p);
}

__device__ __forceinline__ void mma16816(float* c, const uint32_t* a, const uint32_t* b) {
    asm volatile(
        "mma.sync.aligned.m16n8k16.row.col.f32.bf16.bf16.f32 "
        "{%0,%1,%2,%3}, {%4,%5,%6,%7}, {%8,%9}, {%0,%1,%2,%3};"
        : "+f"(c[0]), "+f"(c[1]), "+f"(c[2]), "+f"(c[3])
        : "r"(a[0]), "r"(a[1]), "r"(a[2]), "r"(a[3]), "r"(b[0]), "r"(b[1]));
}

__device__ __forceinline__ void ldsm4(uint32_t* r, uint32_t addr) {
    asm volatile("ldmatrix.sync.aligned.m8n8.x4.shared.b16 {%0,%1,%2,%3}, [%4];"
        : "=r"(r[0]), "=r"(r[1]), "=r"(r[2]), "=r"(r[3]) : "r"(addr));
}

#define CP16(dst, src) \
    asm volatile("cp.async.cg.shared.global [%0], [%1], 16;" :: "r"(dst), "l"(src))
#define CP_COMMIT()  asm volatile("cp.async.commit_group;" ::: "memory")
#define CP_WAIT1()   asm volatile("cp.async.wait_group 1;" ::: "memory")
#define CP_WAIT0()   asm volatile("cp.async.wait_group 0;" ::: "memory")

// ---------------------------------------------------------------------------
// fp32 -> bf16 hi/lo split (elementwise, float4 vectorized)
// ---------------------------------------------------------------------------
__global__ void split_kernel(const float4* __restrict__ in,
                             __nv_bfloat162* __restrict__ hi,
                             __nv_bfloat162* __restrict__ lo, int n4)
{
    int i = blockIdx.x * blockDim.x + threadIdx.x;
    if (i >= n4) return;
    float4 v = in[i];
    bf16 h0 = __float2bfloat16(v.x), h1 = __float2bfloat16(v.y);
    bf16 h2 = __float2bfloat16(v.z), h3 = __float2bfloat16(v.w);
    bf16 l0 = __float2bfloat16(v.x - __bfloat162float(h0));
    bf16 l1 = __float2bfloat16(v.y - __bfloat162float(h1));
    bf16 l2 = __float2bfloat16(v.z - __bfloat162float(h2));
    bf16 l3 = __float2bfloat16(v.w - __bfloat162float(h3));
    hi[2 * i + 0] = __halves2bfloat162(h0, h1);
    hi[2 * i + 1] = __halves2bfloat162(h2, h3);
    lo[2 * i + 0] = __halves2bfloat162(l0, l1);
    lo[2 * i + 1] = __halves2bfloat162(l2, l3);
}

// ---------------------------------------------------------------------------
// Transpose + split: W[K,N] row-major (fp32) -> Wt_hi/lo [N,K] (bf16)
// ---------------------------------------------------------------------------
__global__ void tsplit_kernel(const float* __restrict__ W,
                              bf16* __restrict__ Thi, bf16* __restrict__ Tlo,
                              int K, int N)
{
    __shared__ float tile[32][33];
    int n0 = blockIdx.x * 32, k0 = blockIdx.y * 32;
    int tx = threadIdx.x, ty = threadIdx.y;   // 32 x 8
#pragma unroll
    for (int j = 0; j < 32; j += 8)
        tile[ty + j][tx] = W[(size_t)(k0 + ty + j) * N + n0 + tx];
    __syncthreads();
#pragma unroll
    for (int j = 0; j < 32; j += 8) {
        float v = tile[tx][ty + j];
        bf16 h = __float2bfloat16(v);
        bf16 l = __float2bfloat16(v - __bfloat162float(h));
        size_t o = (size_t)(n0 + ty + j) * K + k0 + tx;
        Thi[o] = h;
        Tlo[o] = l;
    }
}

// ---------------------------------------------------------------------------
// bf16x3 mma.sync GEMM: C[M,N] = Ahi*Bhi^T + Alo*Bhi^T + Ahi*Blo^T (+bias)
// A*: [M,768] row-major bf16.  B*: [N,768] row-major bf16 (pre-transposed).
// CTA tile 128x128, K-chunk 32, cp.async double buffer, 8 warps @ 64x32.
// SMEM rows padded to 80B (40 bf16): conflict-free ldmatrix & cp.async.
// ---------------------------------------------------------------------------
#define ROWB     80                          // padded row bytes (32 bf16 data)
#define TILE_B   (128 * ROWB)                // 10240
#define STAGE_B  (4 * TILE_B)                // Ahi, Alo, Bhi, Blo = 40960
#define SMEM_GEMM (2 * STAGE_B)              // 81920

__global__ __launch_bounds__(256) void gemm_mma(
    const bf16* __restrict__ Ahi, const bf16* __restrict__ Alo,
    const bf16* __restrict__ Bhi, const bf16* __restrict__ Blo,
    float* __restrict__ C, int N, const float* __restrict__ bias)
{
    extern __shared__ char sm[];
    const int tid  = threadIdx.x;
    const int wid  = tid >> 5;
    const int lane = tid & 31;

    const size_t m0 = (size_t)blockIdx.y * 128;
    const size_t n0 = (size_t)blockIdx.x * 128;

    // ---- loader setup: 4 tiles x 64 threads, 8 x 16B chunks per thread ----
    const int ltile = tid >> 6;          // 0:Ahi 1:Alo 2:Bhi 3:Blo
    const int lsub  = tid & 63;
    const int lrow0 = lsub >> 2;         // + i*16
    const int lseg  = lsub & 3;          // 16B segment within 64B row data
    const bf16* lsrc;
    {
        const bf16* s0 = Ahi + m0 * KDIM;
        const bf16* s1 = Alo + m0 * KDIM;
        const bf16* s2 = Bhi + n0 * KDIM;
        const bf16* s3 = Blo + n0 * KDIM;
        lsrc = (ltile == 0) ? s0 : (ltile == 1) ? s1 : (ltile == 2) ? s2 : s3;
    }
    const uint32_t sbase = smem_u32(sm);
    const uint32_t ldst0 = sbase + ltile * TILE_B + lrow0 * ROWB + lseg * 16;
    const bf16* lsrc0 = lsrc + (size_t)lrow0 * KDIM + lseg * 8;

    auto load_stage = [&](int kc, int s) {
        uint32_t d = ldst0 + s * STAGE_B;
        const bf16* g = lsrc0 + kc;
#pragma unroll
        for (int i = 0; i < 8; i++) {
            CP16(d + i * 16 * ROWB, g + (size_t)i * 16 * KDIM);
        }
    };

    // ---- compute setup ----
    const int warp_m = wid & 1;          // 0..1  -> 64 rows
    const int warp_n = wid >> 1;         // 0..3  -> 32 cols
    const int g  = lane >> 3;            // ldmatrix address group
    const int r8 = lane & 7;

    // A frag address (per mt tile of 16 rows): rows r0 + (g&1)*8 + r8, byte (g>>1)*16
    const uint32_t a_off = (uint32_t)((warp_m * 64 + (g & 1) * 8 + r8) * ROWB + (g >> 1) * 16);
    // B frag address (per 16-col group): rows n_base + ((g>>1)&1)*8 + r8, byte (g&1)*16
    const uint32_t b_off = (uint32_t)((warp_n * 32 + ((g >> 1) & 1) * 8 + r8) * ROWB + (g & 1) * 16);

    float acc[4][4][4];
#pragma unroll
    for (int i = 0; i < 4; i++)
#pragma unroll
        for (int j = 0; j < 4; j++)
#pragma unroll
            for (int q = 0; q < 4; q++) acc[i][j][q] = 0.f;

    load_stage(0, 0);
    CP_COMMIT();

    for (int it = 0; it < KDIM / 32; it++) {
        const int s = it & 1;
        if (it + 1 < KDIM / 32) {
            load_stage((it + 1) * 32, s ^ 1);
            CP_COMMIT();
            CP_WAIT1();
        } else {
            CP_WAIT0();
        }
        __syncthreads();

        const uint32_t st = sbase + s * STAGE_B;
#pragma unroll
        for (int kk = 0; kk < 2; kk++) {       // two k16 steps, byte offset kk*32
            const uint32_t kb = kk * 32;
            uint32_t ah[4][4], al[4][4], bh[4][2], bl[4][2];
#pragma unroll
            for (int mt = 0; mt < 4; mt++) {
                ldsm4(ah[mt], st + 0 * TILE_B + a_off + mt * 16 * ROWB + kb);
                ldsm4(al[mt], st + 1 * TILE_B + a_off + mt * 16 * ROWB + kb);
            }
#pragma unroll
            for (int j = 0; j < 2; j++) {      // each covers 2 n8 tiles
                uint32_t t4[4];
                ldsm4(t4, st + 2 * TILE_B + b_off + j * 16 * ROWB + kb);
                bh[j * 2 + 0][0] = t4[0]; bh[j * 2 + 0][1] = t4[1];
                bh[j * 2 + 1][0] = t4[2]; bh[j * 2 + 1][1] = t4[3];
                ldsm4(t4, st + 3 * TILE_B + b_off + j * 16 * ROWB + kb);
                bl[j * 2 + 0][0] = t4[0]; bl[j * 2 + 0][1] = t4[1];
                bl[j * 2 + 1][0] = t4[2]; bl[j * 2 + 1][1] = t4[3];
            }
            // pass 1: hi*hi
#pragma unroll
            for (int mt = 0; mt < 4; mt++)
#pragma unroll
                for (int nt = 0; nt < 4; nt++)
                    mma16816(acc[mt][nt], ah[mt], bh[nt]);
            // pass 2: lo*hi
#pragma unroll
            for (int mt = 0; mt < 4; mt++)
#pragma unroll
                for (int nt = 0; nt < 4; nt++)
                    mma16816(acc[mt][nt], al[mt], bh[nt]);
            // pass 3: hi*lo
#pragma unroll
            for (int mt = 0; mt < 4; mt++)
#pragma unroll
                for (int nt = 0; nt < 4; nt++)
                    mma16816(acc[mt][nt], ah[mt], bl[nt]);
        }
        __syncthreads();
    }

    // ---- epilogue ----
    const int crow = warp_m * 64 + (lane >> 2);
    const int ccol = warp_n * 32 + (lane & 3) * 2;
#pragma unroll
    for (int mt = 0; mt < 4; mt++) {
#pragma unroll
        for (int nt = 0; nt < 4; nt++) {
            float b0 = 0.f, b1 = 0.f;
            if (bias) {
                b0 = __ldg(bias + n0 + ccol + nt * 8);
                b1 = __ldg(bias + n0 + ccol + nt * 8 + 1);
            }
            float2 v0 = {acc[mt][nt][0] + b0, acc[mt][nt][1] + b1};
            float2 v1 = {acc[mt][nt][2] + b0, acc[mt][nt][3] + b1};
            float* p0 = C + (m0 + crow + mt * 16) * (size_t)N + n0 + ccol + nt * 8;
            float* p1 = p0 + 8 * (size_t)N;
            *(float2*)p0 = v0;
            *(float2*)p1 = v1;
        }
    }
}

// ---------------------------------------------------------------------------
// Fused cross-covariance attention core (one CTA per (b,h)).
// Phase 3 emits the bf16 hi/lo split directly for GEMM2.
// ---------------------------------------------------------------------------
__global__ __launch_bounds__(256) void xca_kernel(const float* __restrict__ temperature)
{
    __shared__ float qs[32][48];
    __shared__ float ks[32][48];
    __shared__ float attn[48][52];
    __shared__ float invq[48];
    __shared__ float invk[48];

    const int bh = blockIdx.x;
    const int b = bh >> 4;
    const int h = bh & 15;
    const float* base = g_qkv + (size_t)b * NTOK * (3 * CH) + (size_t)h * HD;
    const int tid = threadIdx.x;
    const int r = tid >> 4;
    const int c = tid & 15;

    float acc[3][3];
#pragma unroll
    for (int i = 0; i < 3; i++)
#pragma unroll
        for (int j = 0; j < 3; j++) acc[i][j] = 0.f;
    float ssq[3] = {0.f, 0.f, 0.f};
    float ssk[3] = {0.f, 0.f, 0.f};

    for (int n0 = 0; n0 < NTOK; n0 += 32) {
        __syncthreads();
#pragma unroll
        for (int i = 0; i < 2; i++) {
            int idx = tid + i * 256;
            if (idx < 384) {
                int n = idx / 12;
                int m = (idx % 12) * 4;
                const float* p = base + (size_t)(n0 + n) * (3 * CH) + m;
                *(float4*)&qs[n][m] = *(const float4*)p;
                *(float4*)&ks[n][m] = *(const float4*)(p + CH);
            }
        }
        __syncthreads();
#pragma unroll 2
        for (int n = 0; n < 32; n++) {
            float q0 = qs[n][3 * r], q1 = qs[n][3 * r + 1], q2 = qs[n][3 * r + 2];
            float k0 = ks[n][3 * c], k1 = ks[n][3 * c + 1], k2 = ks[n][3 * c + 2];
            acc[0][0] = fmaf(q0, k0, acc[0][0]);
            acc[0][1] = fmaf(q0, k1, acc[0][1]);
            acc[0][2] = fmaf(q0, k2, acc[0][2]);
            acc[1][0] = fmaf(q1, k0, acc[1][0]);
            acc[1][1] = fmaf(q1, k1, acc[1][1]);
            acc[1][2] = fmaf(q1, k2, acc[1][2]);
            acc[2][0] = fmaf(q2, k0, acc[2][0]);
            acc[2][1] = fmaf(q2, k1, acc[2][1]);
            acc[2][2] = fmaf(q2, k2, acc[2][2]);
            if (c == 0) {
                ssq[0] = fmaf(q0, q0, ssq[0]);
                ssq[1] = fmaf(q1, q1, ssq[1]);
                ssq[2] = fmaf(q2, q2, ssq[2]);
            }
            if (r == 0) {
                ssk[0] = fmaf(k0, k0, ssk[0]);
                ssk[1] = fmaf(k1, k1, ssk[1]);
                ssk[2] = fmaf(k2, k2, ssk[2]);
            }
        }
    }

    if (c == 0) {
        invq[3 * r + 0] = ssq[0];
        invq[3 * r + 1] = ssq[1];
        invq[3 * r + 2] = ssq[2];
    }
    if (r == 0) {
        invk[3 * c + 0] = ssk[0];
        invk[3 * c + 1] = ssk[1];
        invk[3 * c + 2] = ssk[2];
    }
    __syncthreads();
    if (tid < 48) {
        invq[tid] = 1.f / fmaxf(sqrtf(invq[tid]), 1e-12f);
    } else if (tid < 96) {
        invk[tid - 48] = 1.f / fmaxf(sqrtf(invk[tid - 48]), 1e-12f);
    }
    __syncthreads();

    const float temp = temperature[h];
#pragma unroll
    for (int i = 0; i < 3; i++)
#pragma unroll
        for (int j = 0; j < 3; j++)
            attn[3 * r + i][3 * c + j] =
                acc[i][j] * invq[3 * r + i] * invk[3 * c + j] * temp;
    __syncthreads();

    const int lane = tid & 31;
    const int w = tid >> 5;
    for (int d = w; d < 48; d += 8) {
        float x1 = attn[d][lane];
        float x2 = (lane < 16) ? attn[d][32 + lane] : -1e30f;
        float m = fmaxf(x1, x2);
#pragma unroll
        for (int o = 16; o > 0; o >>= 1)
            m = fmaxf(m, __shfl_xor_sync(0xffffffffu, m, o));
        float p1 = expf(x1 - m);
        float p2 = (lane < 16) ? expf(x2 - m) : 0.f;
        float s = p1 + p2;
#pragma unroll
        for (int o = 16; o > 0; o >>= 1)
            s += __shfl_xor_sync(0xffffffffu, s, o);
        float inv = 1.f / s;
        attn[d][lane] = p1 * inv;
        if (lane < 16) attn[d][32 + lane] = p2 * inv;
    }
    __syncthreads();

    bf16* outhi = g_ahi + (size_t)b * NTOK * CH + (size_t)h * HD;
    bf16* outlo = g_alo + (size_t)b * NTOK * CH + (size_t)h * HD;
    const int d = tid % 48;
    const int vt = tid / 48;
    float areg[48];
    if (tid < 192) {
#pragma unroll
        for (int e = 0; e < 48; e++) areg[e] = attn[d][e];
    }

    for (int n0 = 0; n0 < NTOK; n0 += 16) {
        __syncthreads();
        if (tid < 192) {
            int n = tid / 12;
            int m = (tid % 12) * 4;
            *(float4*)&qs[n][m] =
                *(const float4*)(base + (size_t)(n0 + n) * (3 * CH) + 2 * CH + m);
        }
        __syncthreads();
        if (tid < 192) {
            int nb = vt * 4;
            float o0 = 0.f, o1 = 0.f, o2 = 0.f, o3 = 0.f;
#pragma unroll
            for (int e = 0; e < 48; e++) {
                float a = areg[e];
                o0 = fmaf(a, qs[nb + 0][e], o0);
                o1 = fmaf(a, qs[nb + 1][e], o1);
                o2 = fmaf(a, qs[nb + 2][e], o2);
                o3 = fmaf(a, qs[nb + 3][e], o3);
            }
            float ov[4] = {o0, o1, o2, o3};
#pragma unroll
            for (int j = 0; j < 4; j++) {
                bf16 hh = __float2bfloat16(ov[j]);
                bf16 ll = __float2bfloat16(ov[j] - __bfloat162float(hh));
                size_t off = (size_t)(n0 + nb + j) * CH + d;
                outhi[off] = hh;
                outlo[off] = ll;
            }
        }
    }
}

// ---------------------------------------------------------------------------
// Launch sequence
// ---------------------------------------------------------------------------
extern "C" void kernel_launch(void* const* d_in, const int* in_sizes, int n_in,
                              void* d_out, int out_size)
{
    const float* x           = (const float*)d_in[0];
    const float* qkv_w       = (const float*)d_in[1];
    const float* temperature = (const float*)d_in[2];
    const float* proj_w      = (const float*)d_in[3];
    const float* proj_b      = (const float*)d_in[4];
    float* out = (float*)d_out;

    bf16 *xhi, *xlo, *ahi, *alo, *wqhi, *wqlo, *wphi, *wplo;
    float* qkv_d;
    cudaGetSymbolAddress((void**)&xhi, g_xhi);
    cudaGetSymbolAddress((void**)&xlo, g_xlo);
    cudaGetSymbolAddress((void**)&ahi, g_ahi);
    cudaGetSymbolAddress((void**)&alo, g_alo);
    cudaGetSymbolAddress((void**)&wqhi, g_wqhi);
    cudaGetSymbolAddress((void**)&wqlo, g_wqlo);
    cudaGetSymbolAddress((void**)&wphi, g_wphi);
    cudaGetSymbolAddress((void**)&wplo, g_wplo);
    cudaGetSymbolAddress((void**)&qkv_d, g_qkv);

    cudaFuncSetAttribute(gemm_mma, cudaFuncAttributeMaxDynamicSharedMemorySize, SMEM_GEMM);

    // 1) split x into bf16 hi/lo
    int n4 = MROWS * KDIM / 4;
    split_kernel<<<(n4 + 255) / 256, 256>>>(
        (const float4*)x, (__nv_bfloat162*)xhi, (__nv_bfloat162*)xlo, n4);

    // 2) transpose+split weights
    tsplit_kernel<<<dim3((3 * CH) / 32, KDIM / 32), dim3(32, 8)>>>(
        qkv_w, wqhi, wqlo, KDIM, 3 * CH);
    tsplit_kernel<<<dim3(CH / 32, KDIM / 32), dim3(32, 8)>>>(
        proj_w, wphi, wplo, KDIM, CH);

    // 3) GEMM1: qkv = x @ qkv_w   [50176, 2304]
    gemm_mma<<<dim3((3 * CH) / 128, MROWS / 128), 256, SMEM_GEMM>>>(
        xhi, xlo, wqhi, wqlo, qkv_d, 3 * CH, nullptr);

    // 4) fused XCA (writes att hi/lo bf16)
    xca_kernel<<<BATCH * NH, 256>>>(temperature);

    // 5) GEMM2: out = att @ proj_w + b   [50176, 768]
    gemm_mma<<<dim3(CH / 128, MROWS / 128), 256, SMEM_GEMM>>>(
        ahi, alo, wphi, wplo, out, CH, proj_b);
}